// round 4
// baseline (speedup 1.0000x reference)
#include <cuda_runtime.h>
#include <math.h>

// Problem constants (fixed by the reference)
#define NN   10000            // nodes
#define NB   32               // batch
#define DIN  64
#define DOUT 64
#define FF   128              // DIN + DOUT
#define NE   160000           // edges
#define MM   (NN*NB)          // 320000 "rows" (node-major: m = n*32 + b)
#define BFLT (NB*FF)          // 4096 floats per node
#define V4   (BFLT/4)         // 1024 float4 per node

// ---------------- scratch (device globals; allocation-free) ----------------
__device__ __align__(16) float g_X0[MM*FF];   // concat(inputs, hx), layout [n][b][f]
__device__ __align__(16) float g_X1[MM*FF];   // A(x0)
__device__ __align__(16) float g_X2[MM*FF];   // 2A(x1) - x0
__device__ __align__(16) float g_C0[MM*FF];   // concat(inputs, r*hx)
__device__ __align__(16) float g_C1[MM*FF];
__device__ __align__(16) float g_C2[MM*FF];
__device__ __align__(16) float g_Z [MM*DOUT]; // update gate z
__device__ int   g_cnt[NN];
__device__ int   g_rs [NN+1];   // CSR row starts (by destination row)
__device__ int   g_cur[NN];
__device__ int   g_ecol[NE];
__device__ float g_ew [NE];
__device__ int   g_is64;        // edge_index dtype flag

// ---------------- edge_index dtype detection ----------------
// If data is int64, all values interpreted as int64 lie in [0, NN).
// If data is int32, the int64 interpretation packs two random node ids:
// lo + hi*2^32, which is >= NN unless hi==0 (p=1e-4 per elem).
__global__ void k_detect(const long long* __restrict__ ei) {
    __shared__ int bad;
    if (threadIdx.x == 0) bad = 0;
    __syncthreads();
    long long v = ei[threadIdx.x];         // 256 threads; in-bounds either dtype
    if (v < 0 || v >= NN) atomicOr(&bad, 1);
    __syncthreads();
    if (threadIdx.x == 0) g_is64 = bad ? 0 : 1;
}

// ---------------- CSR construction ----------------
__global__ void k_zero_cnt() {
    int i = blockIdx.x*blockDim.x + threadIdx.x;
    if (i < NN) g_cnt[i] = 0;
}

__global__ void k_hist(const void* __restrict__ eiv) {
    int e = blockIdx.x*blockDim.x + threadIdx.x;
    if (e < NE) {
        int r;
        if (g_is64) r = (int)((const long long*)eiv)[e];
        else        r = ((const int*)eiv)[e];
        atomicAdd(&g_cnt[r], 1);
    }
}

// single-block exclusive scan of 10000 counts
__global__ void k_scan() {
    __shared__ int sums[1024];
    int t = threadIdx.x;
    const int CH = 10;                  // 1024*10 >= 10000
    int base = t*CH;
    int loc[CH];
    int s = 0;
    #pragma unroll
    for (int i = 0; i < CH; i++) {
        int idx = base + i;
        int v = (idx < NN) ? g_cnt[idx] : 0;
        loc[i] = s; s += v;
    }
    sums[t] = s;
    __syncthreads();
    for (int off = 1; off < 1024; off <<= 1) {
        int v = (t >= off) ? sums[t-off] : 0;
        __syncthreads();
        sums[t] += v;
        __syncthreads();
    }
    int prev = (t > 0) ? sums[t-1] : 0;
    #pragma unroll
    for (int i = 0; i < CH; i++) {
        int idx = base + i;
        if (idx < NN) {
            int v = prev + loc[i];
            g_rs[idx] = v;
            g_cur[idx] = v;
        }
    }
    if (t == 1023) g_rs[NN] = sums[1023];
}

__global__ void k_fill(const void* __restrict__ eiv,
                       const float* __restrict__ ew) {
    int e = blockIdx.x*blockDim.x + threadIdx.x;
    if (e < NE) {
        int r, c;
        if (g_is64) {
            r = (int)((const long long*)eiv)[e];
            c = (int)((const long long*)eiv)[NE + e];
        } else {
            r = ((const int*)eiv)[e];
            c = ((const int*)eiv)[NE + e];
        }
        int pos = atomicAdd(&g_cur[r], 1);
        g_ecol[pos] = c;
        g_ew [pos]  = ew[e];
    }
}

// ---------------- build X0 = concat(inputs, hx) in [n][b][f] layout ----------------
__global__ void k_build(const float* __restrict__ in, const float* __restrict__ hx) {
    int n = blockIdx.x;
    for (int i = threadIdx.x; i < NB*DIN; i += 256) {
        int b = i >> 6, f = i & 63;
        g_X0[n*BFLT + b*FF + f]      = in[b*(NN*DIN) + n*DIN + f];
        g_X0[n*BFLT + b*FF + 64 + f] = hx[b*(NN*DOUT) + n*DOUT + f];
    }
}

// ---------------- graph conv (CSR gather-reduce, atomic-free) ----------------
// out[n] = (sub ? -base[n] : 0) + scale * sum_{e in row n} w_e * x[col_e]
__global__ void k_conv(const float4* __restrict__ x,
                       const float4* __restrict__ base,
                       float4* __restrict__ out,
                       float scale, int sub) {
    int n = blockIdx.x;
    int t = threadIdx.x;                 // 256 threads, 4 float4 each
    float4 acc[4];
    if (sub) {
        #pragma unroll
        for (int j = 0; j < 4; j++) {
            float4 v = base[n*V4 + t + j*256];
            acc[j] = make_float4(-v.x, -v.y, -v.z, -v.w);
        }
    } else {
        #pragma unroll
        for (int j = 0; j < 4; j++) acc[j] = make_float4(0.f, 0.f, 0.f, 0.f);
    }
    int e0 = __ldg(&g_rs[n]);
    int e1 = __ldg(&g_rs[n+1]);
    for (int e = e0; e < e1; e++) {
        int c   = __ldg(&g_ecol[e]);
        float w = __ldg(&g_ew[e]) * scale;
        const float4* xp = x + (long long)c*V4;
        #pragma unroll
        for (int j = 0; j < 4; j++) {
            float4 v = __ldg(&xp[t + j*256]);
            acc[j].x = fmaf(w, v.x, acc[j].x);
            acc[j].y = fmaf(w, v.y, acc[j].y);
            acc[j].z = fmaf(w, v.z, acc[j].z);
            acc[j].w = fmaf(w, v.w, acc[j].w);
        }
    }
    #pragma unroll
    for (int j = 0; j < 4; j++) out[n*V4 + t + j*256] = acc[j];
}

// ---------------- GEMM 1: gates ----------------
// G = sigmoid([X0 X1 X2] @ Wg^T + bg)  (M=320000, K=384, N=128)
// epilogue: z -> g_Z ;  g_C0 = [inputs, r*hx]
__global__ __launch_bounds__(256, 2) void k_gates(const float* __restrict__ Wg,
                                                  const float* __restrict__ bg) {
    __shared__ __align__(16) float As[32][132];
    __shared__ __align__(16) float Bs[32][132];
    int tid = threadIdx.x;
    int tx = tid & 15;      // col group (8 cols)
    int ty = tid >> 4;      // row group (8 rows)
    int m0 = blockIdx.x * 128;

    float acc[8][8];
    #pragma unroll
    for (int i = 0; i < 8; i++)
        #pragma unroll
        for (int j = 0; j < 8; j++) acc[i][j] = 0.f;

    const float* bufs[3] = {g_X0, g_X1, g_X2};

    for (int bsel = 0; bsel < 3; bsel++) {
        const float* A = bufs[bsel];
        for (int kt = 0; kt < 128; kt += 32) {
            // A tile: 128 rows x 32 k
            #pragma unroll
            for (int j = 0; j < 4; j++) {
                int q = tid + 256*j;
                int r = q >> 3;
                int kk = (q & 7) << 2;
                float4 v = *(const float4*)&A[(long long)(m0 + r)*FF + kt + kk];
                As[kk+0][r] = v.x; As[kk+1][r] = v.y;
                As[kk+2][r] = v.z; As[kk+3][r] = v.w;
            }
            // B tile: Bs[k][n] = Wg[n][bsel*128 + kt + k]
            #pragma unroll
            for (int j = 0; j < 4; j++) {
                int q = tid + 256*j;
                int nn = q >> 3;
                int kk = (q & 7) << 2;
                float4 v = *(const float4*)&Wg[nn*384 + bsel*128 + kt + kk];
                Bs[kk+0][nn] = v.x; Bs[kk+1][nn] = v.y;
                Bs[kk+2][nn] = v.z; Bs[kk+3][nn] = v.w;
            }
            __syncthreads();
            #pragma unroll
            for (int kk = 0; kk < 32; kk++) {
                float4 a0 = *(const float4*)&As[kk][ty*8];
                float4 a1 = *(const float4*)&As[kk][ty*8 + 4];
                float4 b0 = *(const float4*)&Bs[kk][tx*8];
                float4 b1 = *(const float4*)&Bs[kk][tx*8 + 4];
                float a[8] = {a0.x,a0.y,a0.z,a0.w,a1.x,a1.y,a1.z,a1.w};
                float b[8] = {b0.x,b0.y,b0.z,b0.w,b1.x,b1.y,b1.z,b1.w};
                #pragma unroll
                for (int i = 0; i < 8; i++)
                    #pragma unroll
                    for (int j = 0; j < 8; j++)
                        acc[i][j] = fmaf(a[i], b[j], acc[i][j]);
            }
            __syncthreads();
        }
    }

    // epilogue
    #pragma unroll
    for (int i = 0; i < 8; i++) {
        long long m = m0 + ty*8 + i;
        #pragma unroll
        for (int j = 0; j < 8; j++) {
            int c = tx*8 + j;
            float g = acc[i][j] + __ldg(&bg[c]);
            float s = 1.f / (1.f + expf(-g));
            float x0v = g_X0[m*FF + c];
            if (c < 64) {                 // z ; copy inputs half into x_cand
                g_Z[m*DOUT + c]  = s;
                g_C0[m*FF + c]   = x0v;
            } else {                      // r ; x_cand second half = r*hx
                g_C0[m*FF + c]   = s * x0v;
            }
        }
    }
}

// ---------------- GEMM 2: candidate + final combine ----------------
// cand = tanh([C0 C1 C2] @ Wc^T + bc) ; out = (1-z)*hx + z*cand  (N=64)
__global__ __launch_bounds__(256, 2) void k_cand(const float* __restrict__ Wc,
                                                 const float* __restrict__ bc,
                                                 float* __restrict__ out) {
    __shared__ __align__(16) float As[32][132];
    __shared__ __align__(16) float Bs[32][68];
    int tid = threadIdx.x;
    int tx = tid & 15;      // col group (4 cols)
    int ty = tid >> 4;      // row group (8 rows)
    int m0 = blockIdx.x * 128;

    float acc[8][4];
    #pragma unroll
    for (int i = 0; i < 8; i++)
        #pragma unroll
        for (int j = 0; j < 4; j++) acc[i][j] = 0.f;

    const float* bufs[3] = {g_C0, g_C1, g_C2};

    for (int bsel = 0; bsel < 3; bsel++) {
        const float* A = bufs[bsel];
        for (int kt = 0; kt < 128; kt += 32) {
            #pragma unroll
            for (int j = 0; j < 4; j++) {
                int q = tid + 256*j;
                int r = q >> 3;
                int kk = (q & 7) << 2;
                float4 v = *(const float4*)&A[(long long)(m0 + r)*FF + kt + kk];
                As[kk+0][r] = v.x; As[kk+1][r] = v.y;
                As[kk+2][r] = v.z; As[kk+3][r] = v.w;
            }
            { // B tile: 64 rows x 32 k -> 512 float4, 2 per thread
                #pragma unroll
                for (int j = 0; j < 2; j++) {
                    int q = tid + 256*j;
                    int nn = q >> 3;
                    int kk = (q & 7) << 2;
                    float4 v = *(const float4*)&Wc[nn*384 + bsel*128 + kt + kk];
                    Bs[kk+0][nn] = v.x; Bs[kk+1][nn] = v.y;
                    Bs[kk+2][nn] = v.z; Bs[kk+3][nn] = v.w;
                }
            }
            __syncthreads();
            #pragma unroll
            for (int kk = 0; kk < 32; kk++) {
                float4 a0 = *(const float4*)&As[kk][ty*8];
                float4 a1 = *(const float4*)&As[kk][ty*8 + 4];
                float4 b0 = *(const float4*)&Bs[kk][tx*4];
                float a[8] = {a0.x,a0.y,a0.z,a0.w,a1.x,a1.y,a1.z,a1.w};
                float b[4] = {b0.x,b0.y,b0.z,b0.w};
                #pragma unroll
                for (int i = 0; i < 8; i++)
                    #pragma unroll
                    for (int j = 0; j < 4; j++)
                        acc[i][j] = fmaf(a[i], b[j], acc[i][j]);
            }
            __syncthreads();
        }
    }

    // epilogue: tanh, gate combine, write back in (B, N, 64) layout
    #pragma unroll
    for (int i = 0; i < 8; i++) {
        long long m = m0 + ty*8 + i;
        int n = (int)(m >> 5);
        int b = (int)(m & 31);
        float* op = &out[(long long)b*(NN*DOUT) + n*DOUT + tx*4];
        float res[4];
        #pragma unroll
        for (int j = 0; j < 4; j++) {
            int c = tx*4 + j;
            float cand = tanhf(acc[i][j] + __ldg(&bc[c]));
            float z  = g_Z[m*DOUT + c];
            float hv = g_X0[m*FF + 64 + c];
            res[j] = (1.f - z)*hv + z*cand;
        }
        *(float4*)op = make_float4(res[0], res[1], res[2], res[3]);
    }
}

// ---------------- launch ----------------
extern "C" void kernel_launch(void* const* d_in, const int* in_sizes, int n_in,
                              void* d_out, int out_size) {
    // Resolve inputs by element count (robust to metadata ordering).
    const float* inp = nullptr;   // 20480000 (first occurrence)
    const float* hx  = nullptr;   // 20480000 (second occurrence)
    const void*  ei  = nullptr;   // 320000   (int32 or int64; detected on device)
    const float* ew  = nullptr;   // 160000
    const float* Wg  = nullptr;   // 49152
    const float* Wc  = nullptr;   // 24576
    const float* bg  = nullptr;   // 128
    const float* bc  = nullptr;   // 64
    for (int i = 0; i < n_in; i++) {
        switch (in_sizes[i]) {
            case 20480000: if (!inp) inp = (const float*)d_in[i];
                           else      hx  = (const float*)d_in[i]; break;
            case 320000:   ei = d_in[i];                 break;
            case 160000:   ew = (const float*)d_in[i];   break;
            case 49152:    Wg = (const float*)d_in[i];   break;
            case 24576:    Wc = (const float*)d_in[i];   break;
            case 128:      bg = (const float*)d_in[i];   break;
            case 64:       bc = (const float*)d_in[i];   break;
            default: break;
        }
    }
    float* out = (float*)d_out;

    void *pX0, *pX1, *pX2, *pC0, *pC1, *pC2;
    cudaGetSymbolAddress(&pX0, g_X0);
    cudaGetSymbolAddress(&pX1, g_X1);
    cudaGetSymbolAddress(&pX2, g_X2);
    cudaGetSymbolAddress(&pC0, g_C0);
    cudaGetSymbolAddress(&pC1, g_C1);
    cudaGetSymbolAddress(&pC2, g_C2);

    // edge_index dtype detection + CSR build (deterministic work every call)
    k_detect<<<1, 256>>>((const long long*)ei);
    k_zero_cnt<<<(NN + 255)/256, 256>>>();
    k_hist<<<NE/256, 256>>>(ei);
    k_scan<<<1, 1024>>>();
    k_fill<<<NE/256, 256>>>(ei, ew);

    // x0 = concat(inputs, hx) in [n][b][f]
    k_build<<<NN, 256>>>(inp, hx);

    // first diffusion
    k_conv<<<NN, 256>>>((const float4*)pX0, nullptr,            (float4*)pX1, 1.f, 0);
    k_conv<<<NN, 256>>>((const float4*)pX1, (const float4*)pX0, (float4*)pX2, 2.f, 1);

    // gates GEMM (+ builds x_cand and stores z)
    k_gates<<<MM/128, 256>>>(Wg, bg);

    // second diffusion on x_cand
    k_conv<<<NN, 256>>>((const float4*)pC0, nullptr,            (float4*)pC1, 1.f, 0);
    k_conv<<<NN, 256>>>((const float4*)pC1, (const float4*)pC0, (float4*)pC2, 2.f, 1);

    // candidate GEMM + tanh + gate combine + transpose to (B, N, 64)
    k_cand<<<MM/128, 256>>>(Wc, bc, out);
}

// round 5
// speedup vs baseline: 1.2526x; 1.2526x over previous
#include <cuda_runtime.h>
#include <math.h>

// Problem constants (fixed by the reference)
#define NN   10000            // nodes
#define NB   32               // batch
#define DIN  64
#define DOUT 64
#define FF   128              // DIN + DOUT
#define NE   160000           // edges
#define MM   (NN*NB)          // 320000 "rows" (node-major: m = n*32 + b)
#define BFLT (NB*FF)          // 4096 floats per node
#define V4   (BFLT/4)         // 1024 float4 per node
#define NSLICE 4              // conv feature slices (40 MB L2-resident working set)

typedef unsigned long long u64;

// packed 2xfp32 FMA (Blackwell FFMA2, PTX-only)
#define FMA2(d, a, b) asm("fma.rn.f32x2 %0, %1, %2, %0;" : "+l"(d) : "l"(a), "l"(b))
#define PACK2(d, f)   asm("mov.b64 %0, {%1, %1};" : "=l"(d) : "r"(f))
#define UNPACK2(lo, hi, d) asm("mov.b64 {%0, %1}, %2;" : "=r"(lo), "=r"(hi) : "l"(d))

// ---------------- scratch (device globals; allocation-free) ----------------
__device__ __align__(16) float g_X0[MM*FF];   // concat(inputs, hx), layout [n][b][f]
__device__ __align__(16) float g_X1[MM*FF];   // A(x0)
__device__ __align__(16) float g_X2[MM*FF];   // 2A(x1) - x0
__device__ __align__(16) float g_C0[MM*FF];   // concat(inputs, r*hx)
__device__ __align__(16) float g_C1[MM*FF];
__device__ __align__(16) float g_C2[MM*FF];
__device__ __align__(16) float g_Z [MM*DOUT]; // update gate z
__device__ int    g_cnt[NN];
__device__ int    g_rs [NN+1];   // CSR row starts (by destination row)
__device__ int    g_cur[NN];
__device__ __align__(8) float2 g_epack[NE];   // {col as int bits, weight}
__device__ int    g_is64;        // edge_index dtype flag

// ---------------- edge_index dtype detection ----------------
__global__ void k_detect(const long long* __restrict__ ei) {
    __shared__ int bad;
    if (threadIdx.x == 0) bad = 0;
    __syncthreads();
    long long v = ei[threadIdx.x];         // 256 threads; in-bounds either dtype
    if (v < 0 || v >= NN) atomicOr(&bad, 1);
    __syncthreads();
    if (threadIdx.x == 0) g_is64 = bad ? 0 : 1;
}

// ---------------- CSR construction ----------------
__global__ void k_zero_cnt() {
    int i = blockIdx.x*blockDim.x + threadIdx.x;
    if (i < NN) g_cnt[i] = 0;
}

__global__ void k_hist(const void* __restrict__ eiv) {
    int e = blockIdx.x*blockDim.x + threadIdx.x;
    if (e < NE) {
        int r;
        if (g_is64) r = (int)((const long long*)eiv)[e];
        else        r = ((const int*)eiv)[e];
        atomicAdd(&g_cnt[r], 1);
    }
}

// single-block exclusive scan of 10000 counts
__global__ void k_scan() {
    __shared__ int sums[1024];
    int t = threadIdx.x;
    const int CH = 10;
    int base = t*CH;
    int loc[CH];
    int s = 0;
    #pragma unroll
    for (int i = 0; i < CH; i++) {
        int idx = base + i;
        int v = (idx < NN) ? g_cnt[idx] : 0;
        loc[i] = s; s += v;
    }
    sums[t] = s;
    __syncthreads();
    for (int off = 1; off < 1024; off <<= 1) {
        int v = (t >= off) ? sums[t-off] : 0;
        __syncthreads();
        sums[t] += v;
        __syncthreads();
    }
    int prev = (t > 0) ? sums[t-1] : 0;
    #pragma unroll
    for (int i = 0; i < CH; i++) {
        int idx = base + i;
        if (idx < NN) {
            int v = prev + loc[i];
            g_rs[idx] = v;
            g_cur[idx] = v;
        }
    }
    if (t == 1023) g_rs[NN] = sums[1023];
}

__global__ void k_fill(const void* __restrict__ eiv,
                       const float* __restrict__ ew) {
    int e = blockIdx.x*blockDim.x + threadIdx.x;
    if (e < NE) {
        int r, c;
        if (g_is64) {
            r = (int)((const long long*)eiv)[e];
            c = (int)((const long long*)eiv)[NE + e];
        } else {
            r = ((const int*)eiv)[e];
            c = ((const int*)eiv)[NE + e];
        }
        int pos = atomicAdd(&g_cur[r], 1);
        g_epack[pos] = make_float2(__int_as_float(c), ew[e]);
    }
}

// ---------------- build X0 = concat(inputs, hx) in [n][b][f] layout ----------------
__global__ void k_build(const float* __restrict__ in, const float* __restrict__ hx) {
    int n = blockIdx.x;
    for (int i = threadIdx.x; i < NB*DIN; i += 256) {
        int b = i >> 6, f = i & 63;
        g_X0[(size_t)n*BFLT + b*FF + f]      = in[(size_t)b*(NN*DIN) + n*DIN + f];
        g_X0[(size_t)n*BFLT + b*FF + 64 + f] = hx[(size_t)b*(NN*DOUT) + n*DOUT + f];
    }
}

// ---------------- graph conv (CSR gather-reduce, feature-sliced) ----------------
// out[n] = scale * sum_{e in row n} w_e * x[col_e]  + (sub ? -base[n] : 0)
__global__ __launch_bounds__(256) void k_conv(const float4* __restrict__ x,
                       const float4* __restrict__ base,
                       float4* __restrict__ out,
                       float scale, int sub) {
    int n   = blockIdx.x;
    int idx = blockIdx.y*256 + threadIdx.x;     // float4 index within node
    float4 acc = make_float4(0.f, 0.f, 0.f, 0.f);
    int e0 = __ldg(&g_rs[n]);
    int e1 = __ldg(&g_rs[n+1]);
    int e = e0;
    for (; e + 2 <= e1; e += 2) {
        float2 p0 = __ldg(&g_epack[e]);
        float2 p1 = __ldg(&g_epack[e+1]);
        float4 v0 = __ldg(&x[(size_t)__float_as_int(p0.x)*V4 + idx]);
        float4 v1 = __ldg(&x[(size_t)__float_as_int(p1.x)*V4 + idx]);
        acc.x = fmaf(p0.y, v0.x, acc.x);
        acc.y = fmaf(p0.y, v0.y, acc.y);
        acc.z = fmaf(p0.y, v0.z, acc.z);
        acc.w = fmaf(p0.y, v0.w, acc.w);
        acc.x = fmaf(p1.y, v1.x, acc.x);
        acc.y = fmaf(p1.y, v1.y, acc.y);
        acc.z = fmaf(p1.y, v1.z, acc.z);
        acc.w = fmaf(p1.y, v1.w, acc.w);
    }
    if (e < e1) {
        float2 p0 = __ldg(&g_epack[e]);
        float4 v0 = __ldg(&x[(size_t)__float_as_int(p0.x)*V4 + idx]);
        acc.x = fmaf(p0.y, v0.x, acc.x);
        acc.y = fmaf(p0.y, v0.y, acc.y);
        acc.z = fmaf(p0.y, v0.z, acc.z);
        acc.w = fmaf(p0.y, v0.w, acc.w);
    }
    float4 r;
    if (sub) {
        float4 b = __ldg(&base[(size_t)n*V4 + idx]);
        r = make_float4(fmaf(scale, acc.x, -b.x), fmaf(scale, acc.y, -b.y),
                        fmaf(scale, acc.z, -b.z), fmaf(scale, acc.w, -b.w));
    } else {
        r = make_float4(scale*acc.x, scale*acc.y, scale*acc.z, scale*acc.w);
    }
    __stcs(&out[(size_t)n*V4 + idx], r);
}

// ---------------- fast activations ----------------
__device__ __forceinline__ float fast_sigmoid(float g) {
    return __fdividef(1.f, 1.f + __expf(-g));
}
__device__ __forceinline__ float fast_tanh(float x) {
    float t = __expf(-2.f * fabsf(x));
    float r = __fdividef(1.f - t, 1.f + t);
    return copysignf(r, x);
}

// ---------------- GEMM 1: gates ----------------
// G = sigmoid([X0 X1 X2] @ Wg^T + bg)  (M=320000, K=384, N=128)
// epilogue: z -> g_Z ;  g_C0 = [inputs, r*hx]
__global__ __launch_bounds__(256, 2) void k_gates(const float* __restrict__ Wg,
                                                  const float* __restrict__ bg) {
    __shared__ __align__(16) float As[32][132];
    __shared__ __align__(16) float Bs[32][132];
    int tid = threadIdx.x;
    int tx = tid & 15;      // col group (8 cols = 4 pairs)
    int ty = tid >> 4;      // row group (8 rows)
    int m0 = blockIdx.x * 128;

    u64 acc2[8][4];
    #pragma unroll
    for (int i = 0; i < 8; i++)
        #pragma unroll
        for (int j = 0; j < 4; j++) acc2[i][j] = 0ULL;

    const float* bufs[3] = {g_X0, g_X1, g_X2};

    for (int bsel = 0; bsel < 3; bsel++) {
        const float* A = bufs[bsel];
        for (int kt = 0; kt < 128; kt += 32) {
            // A tile: 128 rows x 32 k (transposed store)
            #pragma unroll
            for (int j = 0; j < 4; j++) {
                int q = tid + 256*j;
                int r = q >> 3;
                int kk = (q & 7) << 2;
                float4 v = *(const float4*)&A[(size_t)(m0 + r)*FF + kt + kk];
                As[kk+0][r] = v.x; As[kk+1][r] = v.y;
                As[kk+2][r] = v.z; As[kk+3][r] = v.w;
            }
            // B tile: Bs[k][n] = Wg[n][bsel*128 + kt + k]
            #pragma unroll
            for (int j = 0; j < 4; j++) {
                int q = tid + 256*j;
                int nn = q >> 3;
                int kk = (q & 7) << 2;
                float4 v = *(const float4*)&Wg[nn*384 + bsel*128 + kt + kk];
                Bs[kk+0][nn] = v.x; Bs[kk+1][nn] = v.y;
                Bs[kk+2][nn] = v.z; Bs[kk+3][nn] = v.w;
            }
            __syncthreads();
            #pragma unroll
            for (int kk = 0; kk < 32; kk++) {
                float4 a0 = *(const float4*)&As[kk][ty*8];
                float4 a1 = *(const float4*)&As[kk][ty*8 + 4];
                const u64* bp = (const u64*)&Bs[kk][tx*8];
                u64 b0 = bp[0], b1 = bp[1], b2 = bp[2], b3 = bp[3];
                float av[8] = {a0.x,a0.y,a0.z,a0.w,a1.x,a1.y,a1.z,a1.w};
                #pragma unroll
                for (int i = 0; i < 8; i++) {
                    u64 ai; PACK2(ai, __float_as_uint(av[i]));
                    FMA2(acc2[i][0], ai, b0);
                    FMA2(acc2[i][1], ai, b1);
                    FMA2(acc2[i][2], ai, b2);
                    FMA2(acc2[i][3], ai, b3);
                }
            }
            __syncthreads();
        }
    }

    // epilogue
    #pragma unroll
    for (int i = 0; i < 8; i++) {
        size_t m = (size_t)(m0 + ty*8 + i);
        #pragma unroll
        for (int jj = 0; jj < 4; jj++) {
            unsigned lo, hi;
            UNPACK2(lo, hi, acc2[i][jj]);
            float vv[2] = {__uint_as_float(lo), __uint_as_float(hi)};
            #pragma unroll
            for (int h = 0; h < 2; h++) {
                int c = tx*8 + jj*2 + h;
                float s = fast_sigmoid(vv[h] + __ldg(&bg[c]));
                float x0v = g_X0[m*FF + c];
                if (c < 64) {                 // z ; copy inputs half into x_cand
                    g_Z[m*DOUT + c] = s;
                    g_C0[m*FF + c]  = x0v;
                } else {                      // r ; x_cand second half = r*hx
                    g_C0[m*FF + c]  = s * x0v;
                }
            }
        }
    }
}

// ---------------- GEMM 2: candidate + final combine ----------------
// cand = tanh([C0 C1 C2] @ Wc^T + bc) ; out = (1-z)*hx + z*cand  (N=64)
__global__ __launch_bounds__(256, 2) void k_cand(const float* __restrict__ Wc,
                                                 const float* __restrict__ bc,
                                                 float* __restrict__ out) {
    __shared__ __align__(16) float As[32][132];
    __shared__ __align__(16) float Bs[32][68];
    int tid = threadIdx.x;
    int tx = tid & 15;      // col group (4 cols = 2 pairs)
    int ty = tid >> 4;      // row group (8 rows)
    int m0 = blockIdx.x * 128;

    u64 acc2[8][2];
    #pragma unroll
    for (int i = 0; i < 8; i++) {
        acc2[i][0] = 0ULL; acc2[i][1] = 0ULL;
    }

    const float* bufs[3] = {g_C0, g_C1, g_C2};

    for (int bsel = 0; bsel < 3; bsel++) {
        const float* A = bufs[bsel];
        for (int kt = 0; kt < 128; kt += 32) {
            #pragma unroll
            for (int j = 0; j < 4; j++) {
                int q = tid + 256*j;
                int r = q >> 3;
                int kk = (q & 7) << 2;
                float4 v = *(const float4*)&A[(size_t)(m0 + r)*FF + kt + kk];
                As[kk+0][r] = v.x; As[kk+1][r] = v.y;
                As[kk+2][r] = v.z; As[kk+3][r] = v.w;
            }
            { // B tile: 64 rows x 32 k -> 512 float4, 2 per thread
                #pragma unroll
                for (int j = 0; j < 2; j++) {
                    int q = tid + 256*j;
                    int nn = q >> 3;
                    int kk = (q & 7) << 2;
                    float4 v = *(const float4*)&Wc[nn*384 + bsel*128 + kt + kk];
                    Bs[kk+0][nn] = v.x; Bs[kk+1][nn] = v.y;
                    Bs[kk+2][nn] = v.z; Bs[kk+3][nn] = v.w;
                }
            }
            __syncthreads();
            #pragma unroll
            for (int kk = 0; kk < 32; kk++) {
                float4 a0 = *(const float4*)&As[kk][ty*8];
                float4 a1 = *(const float4*)&As[kk][ty*8 + 4];
                const u64* bp = (const u64*)&Bs[kk][tx*4];
                u64 b0 = bp[0], b1 = bp[1];
                float av[8] = {a0.x,a0.y,a0.z,a0.w,a1.x,a1.y,a1.z,a1.w};
                #pragma unroll
                for (int i = 0; i < 8; i++) {
                    u64 ai; PACK2(ai, __float_as_uint(av[i]));
                    FMA2(acc2[i][0], ai, b0);
                    FMA2(acc2[i][1], ai, b1);
                }
            }
            __syncthreads();
        }
    }

    // epilogue: tanh, gate combine, write back in (B, N, 64) layout
    #pragma unroll
    for (int i = 0; i < 8; i++) {
        size_t m = (size_t)(m0 + ty*8 + i);
        int n = (int)(m >> 5);
        int b = (int)(m & 31);
        float* op = &out[(size_t)b*(NN*DOUT) + n*DOUT + tx*4];
        float res[4];
        #pragma unroll
        for (int jj = 0; jj < 2; jj++) {
            unsigned lo, hi;
            UNPACK2(lo, hi, acc2[i][jj]);
            float vv[2] = {__uint_as_float(lo), __uint_as_float(hi)};
            #pragma unroll
            for (int h = 0; h < 2; h++) {
                int c = tx*4 + jj*2 + h;
                float cand = fast_tanh(vv[h] + __ldg(&bc[c]));
                float z  = g_Z[m*DOUT + c];
                float hv = g_X0[m*FF + 64 + c];
                res[jj*2 + h] = (1.f - z)*hv + z*cand;
            }
        }
        *(float4*)op = make_float4(res[0], res[1], res[2], res[3]);
    }
}

// ---------------- launch ----------------
extern "C" void kernel_launch(void* const* d_in, const int* in_sizes, int n_in,
                              void* d_out, int out_size) {
    // Resolve inputs by element count (robust to metadata ordering).
    const float* inp = nullptr;   // 20480000 (first occurrence)
    const float* hx  = nullptr;   // 20480000 (second occurrence)
    const void*  ei  = nullptr;   // 320000   (int32 or int64; detected on device)
    const float* ew  = nullptr;   // 160000
    const float* Wg  = nullptr;   // 49152
    const float* Wc  = nullptr;   // 24576
    const float* bg  = nullptr;   // 128
    const float* bc  = nullptr;   // 64
    for (int i = 0; i < n_in; i++) {
        switch (in_sizes[i]) {
            case 20480000: if (!inp) inp = (const float*)d_in[i];
                           else      hx  = (const float*)d_in[i]; break;
            case 320000:   ei = d_in[i];                 break;
            case 160000:   ew = (const float*)d_in[i];   break;
            case 49152:    Wg = (const float*)d_in[i];   break;
            case 24576:    Wc = (const float*)d_in[i];   break;
            case 128:      bg = (const float*)d_in[i];   break;
            case 64:       bc = (const float*)d_in[i];   break;
            default: break;
        }
    }
    float* out = (float*)d_out;

    void *pX0, *pX1, *pX2, *pC0, *pC1, *pC2;
    cudaGetSymbolAddress(&pX0, g_X0);
    cudaGetSymbolAddress(&pX1, g_X1);
    cudaGetSymbolAddress(&pX2, g_X2);
    cudaGetSymbolAddress(&pC0, g_C0);
    cudaGetSymbolAddress(&pC1, g_C1);
    cudaGetSymbolAddress(&pC2, g_C2);

    // edge_index dtype detection + CSR build (deterministic work every call)
    k_detect<<<1, 256>>>((const long long*)ei);
    k_zero_cnt<<<(NN + 255)/256, 256>>>();
    k_hist<<<NE/256, 256>>>(ei);
    k_scan<<<1, 1024>>>();
    k_fill<<<NE/256, 256>>>(ei, ew);

    // x0 = concat(inputs, hx) in [n][b][f]
    k_build<<<NN, 256>>>(inp, hx);

    dim3 cgrid(NN, NSLICE);
    // first diffusion
    k_conv<<<cgrid, 256>>>((const float4*)pX0, nullptr,            (float4*)pX1, 1.f, 0);
    k_conv<<<cgrid, 256>>>((const float4*)pX1, (const float4*)pX0, (float4*)pX2, 2.f, 1);

    // gates GEMM (+ builds x_cand and stores z)
    k_gates<<<MM/128, 256>>>(Wg, bg);

    // second diffusion on x_cand
    k_conv<<<cgrid, 256>>>((const float4*)pC0, nullptr,            (float4*)pC1, 1.f, 0);
    k_conv<<<cgrid, 256>>>((const float4*)pC1, (const float4*)pC0, (float4*)pC2, 2.f, 1);

    // candidate GEMM + tanh + gate combine + transpose to (B, N, 64)
    k_cand<<<MM/128, 256>>>(Wc, bc, out);
}